// round 8
// baseline (speedup 1.0000x reference)
#include <cuda_runtime.h>
#include <math.h>

#define NG 192
#define TXT 8            // threads x
#define TYT 4            // threads y
#define TZT 8            // threads z
#define XV  4            // x-voxels per thread
#define VXB (TXT * XV)   // 32 voxels per block in x
#define TCX 9            // u32 per packed row (36 bytes)
#define RSTRIDE 10       // row stride in u32 (pad)
#define TYH (TYT + 4)    // 8
#define TZH (TZT + 4)    // 12
#define NROWS (TYH * TZH)        // 96
#define ENTRIES (NROWS * TCX)    // 864 per axis
#define NTOT (NG * NG * NG)

#define KN   500000.0f
#define MU   0.5f
#define EPSF 1e-4f
#define FULLMASK 0xffffffffu

__device__ __forceinline__ int wrapN(int v) {
    if (v < 0) v += NG;
    if (v >= NG) v -= NG;
    return v;
}

// exact per-voxel evaluation + store (rare path)
__device__ __noinline__ void exact_voxel_store(
    int ga, int gb, int gc, float two_d, float eta,
    const float* __restrict__ xg, const float* __restrict__ yg,
    const float* __restrict__ zg, const float* __restrict__ vxg,
    const float* __restrict__ vyg, const float* __restrict__ vzg,
    float* __restrict__ out)
{
    const float two_d2 = two_d * two_d;
    const int gidx = (ga * NG + gb) * NG + gc;
    const float px = xg[gidx], py = yg[gidx], pz = zg[gidx];
    const float pvx = vxg[gidx], pvy = vyg[gidx], pvz = vzg[gidx];
    float fxc = 0.f, fyc = 0.f, fzc = 0.f;
    float fxd = 0.f, fyd = 0.f, fzd = 0.f;
    float frx = 0.f, fry = 0.f, frz = 0.f;
    #pragma unroll 1
    for (int oz = -2; oz <= 2; oz++) {
        const int na = wrapN(ga + oz);
        #pragma unroll 1
        for (int oy = -2; oy <= 2; oy++) {
            const int nb = wrapN(gb + oy);
            const int rowb = (na * NG + nb) * NG;
            #pragma unroll 1
            for (int ox = -2; ox <= 2; ox++) {
                const int nc = wrapN(gc + ox);
                const int nidx = rowb + nc;
                const float dx = px - xg[nidx];
                const float dy = py - yg[nidx];
                const float dz = pz - zg[nidx];
                const float d2 = fmaf(dz, dz, fmaf(dy, dy, dx * dx));
                // d2 == 0 (incl. self) contributes exactly 0 -> skip
                const bool hit = (d2 < two_d2) && (d2 > 0.0f);
                if (hit) {
                    const float dist = sqrtf(d2);
                    const float safe = fmaxf(EPSF, dist);
                    const float inv  = 1.0f / safe;
                    const float coef = KN * (dist - two_d) * inv;
                    fxc += coef * dx;
                    fyc += coef * dy;
                    fzc += coef * dz;
                    const float dvx = pvx - vxg[nidx];
                    const float dvy = pvy - vyg[nidx];
                    const float dvz = pvz - vzg[nidx];
                    const float vn  = (dvx * dx + dvy * dy + dvz * dz) * inv;
                    const float c2  = eta * vn * inv;
                    fxd += c2 * dx;
                    fyd += c2 * dy;
                    fzd += c2 * dz;
                }
            }
        }
    }
    // friction: only the LAST scan shift s=(2,2,2) survives, i.e. neighbor
    // offset (-2,-2,-2), evaluated against the fully accumulated sums.
    {
        const int na = wrapN(ga - 2);
        const int nb = wrapN(gb - 2);
        const int nc = wrapN(gc - 2);
        const int nidx = (na * NG + nb) * NG + nc;
        const float dx = px - xg[nidx];
        const float dy = py - yg[nidx];
        const float dz = pz - zg[nidx];
        const float d2 = fmaf(dz, dz, fmaf(dy, dy, dx * dx));
        if (d2 < two_d2) {
            const float dvx = pvx - vxg[nidx];
            const float dvy = pvy - vyg[nidx];
            const float dvz = pvz - vzg[nidx];
            frx = -(fabsf(fabsf(MU * fyc) + fabsf(MU * fzc) - MU * fxd)
                    * dvx / fmaxf(EPSF, fabsf(dvx)));
            fry = -(fabsf(fabsf(MU * fxc) + fabsf(MU * fzc) - MU * fyd)
                    * dvy / fmaxf(EPSF, fabsf(dvy)));
            // NB: reference uses diffvy in the z-friction numerator (kept).
            frz = -(fabsf(fabsf(MU * fxc) + fabsf(MU * fyc) - MU * fzd)
                    * dvy / fmaxf(EPSF, fabsf(dvz)));
        }
    }
    float* o = out + gidx;
    o[0 * NTOT] = fxc;
    o[1 * NTOT] = fyc;
    o[2 * NTOT] = fzc;
    o[3 * NTOT] = fxd;
    o[4 * NTOT] = fyd;
    o[5 * NTOT] = fzd;
    o[6 * NTOT] = frx;
    o[7 * NTOT] = fry;
    o[8 * NTOT] = frz;
}

__global__ __launch_bounds__(TXT * TYT * TZT, 6)
void dem_kernel(const float* __restrict__ xg, const float* __restrict__ yg,
                const float* __restrict__ zg, const float* __restrict__ vxg,
                const float* __restrict__ vyg, const float* __restrict__ vzg,
                const float* __restrict__ dptr, float* __restrict__ out,
                float eta)
{
    // planar packed floor-byte rows: entry (r, u) = 4 x-floors at tile x 4u..4u+3
    __shared__ unsigned sxp[NROWS * RSTRIDE];
    __shared__ unsigned syp[NROWS * RSTRIDE];
    __shared__ unsigned szp[NROWS * RSTRIDE];

    const int tx = threadIdx.x, ty = threadIdx.y, tz = threadIdx.z;
    const int bx0 = blockIdx.x * VXB;
    const int by0 = blockIdx.y * TYT;
    const int bz0 = blockIdx.z * TZT;
    const int tid = (tz * TYT + ty) * TXT + tx;
    const int NTHR = TXT * TYT * TZT;

    // --- cooperative packed-key build (wraparound halo) ---
    #pragma unroll 1
    for (int ax = 0; ax < 3; ax++) {
        const float* g = (ax == 0) ? xg : (ax == 1) ? yg : zg;
        unsigned* s = (ax == 0) ? sxp : (ax == 1) ? syp : szp;
        for (int e = tid; e < ENTRIES; e += NTHR) {
            int r = e / TCX, u = e % TCX;
            int zt = r / TYH, yt = r % TYH;
            int gz = wrapN(bz0 + zt - 2);
            int gy = wrapN(by0 + yt - 2);
            const float* rowp = g + (gz * NG + gy) * NG;
            unsigned b0 = (unsigned)(int)rowp[wrapN(bx0 + 4 * u - 2)];
            unsigned b1 = (unsigned)(int)rowp[wrapN(bx0 + 4 * u - 1)];
            unsigned b2 = (unsigned)(int)rowp[wrapN(bx0 + 4 * u + 0)];
            unsigned b3 = (unsigned)(int)rowp[wrapN(bx0 + 4 * u + 1)];
            s[r * RSTRIDE + u] = b0 | (b1 << 8) | (b2 << 16) | (b3 << 24);
        }
    }
    __syncthreads();

    const float d     = *dptr;
    const float two_d = 2.0f * d;
    // byte-filter validity: |dx| < two_d <= 1 => |floor diff| <= 1 per axis
    const bool filter_ok = (two_d <= 1.0f);

    // center row / strip: bytes 4tx..4tx+7 = u32 idx tx, tx+1; centers at +2..+5
    const int rc = (tz + 2) * TYH + (ty + 2);
    const int bi = rc * RSTRIDE + tx;
    const unsigned cpx = __byte_perm(sxp[bi], sxp[bi + 1], 0x5432);
    const unsigned cpy = __byte_perm(syp[bi], syp[bi + 1], 0x5432);
    const unsigned cpz = __byte_perm(szp[bi], szp[bi + 1], 0x5432);

    // ---- SIMD byte prefilter: bytes of acc = per-center min over offsets ----
    unsigned acc = 0xFFFFFFFFu;
    #pragma unroll
    for (int oz = -2; oz <= 2; oz++) {
        #pragma unroll
        for (int oy = -2; oy <= 2; oy++) {
            const int ro = bi + (oz * TYH + oy) * RSTRIDE;
            const unsigned Ax = sxp[ro], Bx = sxp[ro + 1];
            const unsigned Ay = syp[ro], By = syp[ro + 1];
            const unsigned Az = szp[ro], Bz = szp[ro + 1];
            #pragma unroll
            for (int s = 0; s < 5; s++) {     // window start byte = ox + 2
                unsigned wx, wy, wz;
                if (s == 0)      { wx = Ax; wy = Ay; wz = Az; }
                else if (s == 4) { wx = Bx; wy = By; wz = Bz; }
                else {
                    const unsigned sel = 0x3210u + 0x1111u * s;
                    wx = __byte_perm(Ax, Bx, sel);
                    wy = __byte_perm(Ay, By, sel);
                    wz = __byte_perm(Az, Bz, sel);
                }
                // per byte: OR of the 3 axis |floor diffs|; <=1 iff each <=1
                const unsigned comb = __vabsdiffu4(cpx, wx)
                                    | __vabsdiffu4(cpy, wy)
                                    | __vabsdiffu4(cpz, wz);
                if (!(oz == 0 && oy == 0 && s == 2))   // skip the 4 self pairs
                    acc = __vminu4(acc, comb);
            }
        }
    }

    unsigned need4 = __vcmpleu4(acc, 0x01010101u);   // 0xFF per hit center
    if (!filter_ok) need4 = 0xFFFFFFFFu;

    // ---- outputs: vector zero-stores always; exact path overwrites (rare) ----
    const int gz = bz0 + tz, gy = by0 + ty, gx0 = bx0 + 4 * tx;
    const int gidx = (gz * NG + gy) * NG + gx0;
    const float4 z4 = make_float4(0.f, 0.f, 0.f, 0.f);
    #pragma unroll
    for (int k = 0; k < 9; k++)
        *(float4*)(out + k * NTOT + gidx) = z4;

    if (__any_sync(FULLMASK, need4 != 0u)) {
        #pragma unroll 1
        for (int c = 0; c < 4; c++) {
            if ((need4 >> (8 * c)) & 0xFFu)
                exact_voxel_store(gz, gy, gx0 + c, two_d, eta,
                                  xg, yg, zg, vxg, vyg, vzg, out);
        }
    }
}

extern "C" void kernel_launch(void* const* d_in, const int* in_sizes, int n_in,
                              void* d_out, int out_size)
{
    const float* xg   = (const float*)d_in[0];
    const float* yg   = (const float*)d_in[1];
    const float* zg   = (const float*)d_in[2];
    const float* vxg  = (const float*)d_in[3];
    const float* vyg  = (const float*)d_in[4];
    const float* vzg  = (const float*)d_in[5];
    const float* dptr = (const float*)d_in[6];
    float* out = (float*)d_out;

    // ETA = 2*gamma*sqrt(KN), gamma = alpha/sqrt(alpha^2+1), alpha = -ln(0.7)/pi
    const double alpha = -log(0.7) / M_PI;
    const double gam   = alpha / sqrt(alpha * alpha + 1.0);
    const float  eta   = (float)(2.0 * gam * sqrt(500000.0));

    dim3 block(TXT, TYT, TZT);
    dim3 grid(NG / VXB, NG / TYT, NG / TZT);
    dem_kernel<<<grid, block>>>(xg, yg, zg, vxg, vyg, vzg, dptr, out, eta);
}

// round 9
// speedup vs baseline: 1.6060x; 1.6060x over previous
#include <cuda_runtime.h>
#include <math.h>

#define NG 192
#define BXT 32           // threads x
#define BYT 4            // threads y (2 y-voxels each)
#define BZT 4            // threads z
#define VYB (BYT * 2)    // 8 voxels y per block
#define TX  (BXT + 4)    // 36
#define TYH (VYB + 4)    // 12
#define TZH (BZT + 4)    // 8
#define TILE (TX * TYH * TZH)  // 3456
#define NTOT (NG * NG * NG)

#define KN   500000.0f
#define MU   0.5f
#define EPSF 1e-4f
#define FULLMASK 0xffffffffu
#define BMASK 0x00FEFEFEu

__device__ __forceinline__ int wrapN(int v) {
    if (v < 0) v += NG;
    if (v >= NG) v -= NG;
    return v;
}

// exact per-voxel evaluation + store (rare path, global reads only)
__device__ __noinline__ void exact_voxel_store(
    int ga, int gb, int gc, float two_d, float eta,
    const float* __restrict__ xg, const float* __restrict__ yg,
    const float* __restrict__ zg, const float* __restrict__ vxg,
    const float* __restrict__ vyg, const float* __restrict__ vzg,
    float* __restrict__ out)
{
    const float two_d2 = two_d * two_d;
    const int gidx = (ga * NG + gb) * NG + gc;
    const float px = xg[gidx], py = yg[gidx], pz = zg[gidx];
    const float pvx = vxg[gidx], pvy = vyg[gidx], pvz = vzg[gidx];
    float fxc = 0.f, fyc = 0.f, fzc = 0.f;
    float fxd = 0.f, fyd = 0.f, fzd = 0.f;
    float frx = 0.f, fry = 0.f, frz = 0.f;
    #pragma unroll 1
    for (int oz = -2; oz <= 2; oz++) {
        const int na = wrapN(ga + oz);
        #pragma unroll 1
        for (int oy = -2; oy <= 2; oy++) {
            const int nb = wrapN(gb + oy);
            const int rowb = (na * NG + nb) * NG;
            #pragma unroll 1
            for (int ox = -2; ox <= 2; ox++) {
                const int nc = wrapN(gc + ox);
                const int nidx = rowb + nc;
                const float dx = px - xg[nidx];
                const float dy = py - yg[nidx];
                const float dz = pz - zg[nidx];
                const float d2 = fmaf(dz, dz, fmaf(dy, dy, dx * dx));
                // d2 == 0 (incl. self) contributes exactly 0 -> skip
                const bool hit = (d2 < two_d2) && (d2 > 0.0f);
                if (hit) {
                    const float dist = sqrtf(d2);
                    const float safe = fmaxf(EPSF, dist);
                    const float inv  = 1.0f / safe;
                    const float coef = KN * (dist - two_d) * inv;
                    fxc += coef * dx;
                    fyc += coef * dy;
                    fzc += coef * dz;
                    const float dvx = pvx - vxg[nidx];
                    const float dvy = pvy - vyg[nidx];
                    const float dvz = pvz - vzg[nidx];
                    const float vn  = (dvx * dx + dvy * dy + dvz * dz) * inv;
                    const float c2  = eta * vn * inv;
                    fxd += c2 * dx;
                    fyd += c2 * dy;
                    fzd += c2 * dz;
                }
            }
        }
    }
    // friction: only the LAST scan shift s=(2,2,2) survives, i.e. neighbor
    // offset (-2,-2,-2), evaluated against the fully accumulated sums.
    {
        const int na = wrapN(ga - 2);
        const int nb = wrapN(gb - 2);
        const int nc = wrapN(gc - 2);
        const int nidx = (na * NG + nb) * NG + nc;
        const float dx = px - xg[nidx];
        const float dy = py - yg[nidx];
        const float dz = pz - zg[nidx];
        const float d2 = fmaf(dz, dz, fmaf(dy, dy, dx * dx));
        if (d2 < two_d2) {
            const float dvx = pvx - vxg[nidx];
            const float dvy = pvy - vyg[nidx];
            const float dvz = pvz - vzg[nidx];
            frx = -(fabsf(fabsf(MU * fyc) + fabsf(MU * fzc) - MU * fxd)
                    * dvx / fmaxf(EPSF, fabsf(dvx)));
            fry = -(fabsf(fabsf(MU * fxc) + fabsf(MU * fzc) - MU * fyd)
                    * dvy / fmaxf(EPSF, fabsf(dvy)));
            // NB: reference uses diffvy in the z-friction numerator (kept).
            frz = -(fabsf(fabsf(MU * fxc) + fabsf(MU * fyc) - MU * fzd)
                    * dvy / fmaxf(EPSF, fabsf(dvz)));
        }
    }
    float* o = out + gidx;
    o[0 * NTOT] = fxc;
    o[1 * NTOT] = fyc;
    o[2 * NTOT] = fzc;
    o[3 * NTOT] = fxd;
    o[4 * NTOT] = fyd;
    o[5 * NTOT] = fzd;
    o[6 * NTOT] = frx;
    o[7 * NTOT] = fry;
    o[8 * NTOT] = frz;
}

__global__ __launch_bounds__(BXT * BYT * BZT, 3)
void dem_kernel(const float* __restrict__ xg, const float* __restrict__ yg,
                const float* __restrict__ zg, const float* __restrict__ vxg,
                const float* __restrict__ vyg, const float* __restrict__ vzg,
                const float* __restrict__ dptr, float* __restrict__ out,
                float eta)
{
    __shared__ unsigned qpk[TILE];   // bytes: (floor(x), floor(y), floor(z), 0)

    const int lx = threadIdx.x, ly = threadIdx.y, lz = threadIdx.z;
    const int bx0 = blockIdx.x * BXT;
    const int by0 = blockIdx.y * VYB;
    const int bz0 = blockIdx.z * BZT;
    const int tid = (lz * BYT + ly) * BXT + lx;
    const int NTHR = BXT * BYT * BZT;

    // --- cooperative halo key build (wraparound) ---
    for (int idx = tid; idx < TILE; idx += NTHR) {
        int tx = idx % TX;
        int r  = idx / TX;
        int ty = r % TYH;
        int tz = r / TYH;
        int gx = wrapN(bx0 + tx - 2);
        int gy = wrapN(by0 + ty - 2);
        int gz = wrapN(bz0 + tz - 2);
        int g = (gz * NG + gy) * NG + gx;
        // coords in [0, 192): floors fit a byte
        qpk[idx] = (unsigned)(int)xg[g] | ((unsigned)(int)yg[g] << 8)
                 | ((unsigned)(int)zg[g] << 16);
    }
    __syncthreads();

    const float d     = *dptr;
    const float two_d = 2.0f * d;
    // byte-filter validity: |dx| < two_d <= 1 => |floor diff| <= 1 per axis
    const bool filter_ok = (two_d <= 1.0f);

    const int cz = lz + 2, cx = lx + 2;
    const int cyA = 2 * ly + 2;                 // center A row; B = cyA+1
    const int cidxA = (cz * TYH + cyA) * TX + cx;
    const unsigned pqA = qpk[cidxA];
    const unsigned pqB = qpk[cidxA + TX];

    // ---- byte prefilter: 6 rows/oz serve both centers (4 rows shared) ----
    unsigned a0 = ~0u, a1 = ~0u, a2 = ~0u, a3 = ~0u;   // center A min-accs
    unsigned b0 = ~0u, b1 = ~0u, b2 = ~0u, b3 = ~0u;   // center B
    if (filter_ok) {
        // base of row r(0..5) at oz: rows cover cyA-2 .. cyA+3
        const int base0 = ((cz - 2) * TYH + (cyA - 2)) * TX + cx;
        #pragma unroll
        for (int oz = 0; oz < 5; oz++) {
            #pragma unroll
            for (int r = 0; r < 6; r++) {
                const int ro = base0 + (oz * TYH + r) * TX;
                const unsigned k0 = qpk[ro - 2];
                const unsigned k1 = qpk[ro - 1];
                const unsigned k2 = qpk[ro    ];
                const unsigned k3 = qpk[ro + 1];
                const unsigned k4 = qpk[ro + 2];
                #define TST(M, P, K) M = min(M, __vabsdiffu4(P, K) & BMASK)
                if (r <= 4) {                        // A rows: r = 0..4
                    TST(a0, pqA, k0);
                    TST(a1, pqA, k1);
                    if (!(oz == 2 && r == 2)) TST(a2, pqA, k2);  // A self
                    TST(a3, pqA, k3);
                    TST(a0, pqA, k4);
                }
                if (r >= 1) {                        // B rows: r = 1..5
                    TST(b0, pqB, k0);
                    TST(b1, pqB, k1);
                    if (!(oz == 2 && r == 3)) TST(b2, pqB, k2);  // B self
                    TST(b3, pqB, k3);
                    TST(b0, pqB, k4);
                }
                #undef TST
            }
        }
    }

    const bool needA = !filter_ok || (min(min(a0, a1), min(a2, a3)) == 0u);
    const bool needB = !filter_ok || (min(min(b0, b1), min(b2, b3)) == 0u);

    const int gz = bz0 + lz, gx = bx0 + lx;
    const int gyA = by0 + 2 * ly;
    const int gidxA = (gz * NG + gyA) * NG + gx;
    const int gidxB = gidxA + NG;

    if (__any_sync(FULLMASK, needA || needB)) {
        // rare warp: zero both, then exact-overwrite the flagged centers
        #pragma unroll
        for (int k = 0; k < 9; k++) {
            out[k * NTOT + gidxA] = 0.f;
            out[k * NTOT + gidxB] = 0.f;
        }
        if (needA)
            exact_voxel_store(gz, gyA, gx, two_d, eta,
                              xg, yg, zg, vxg, vyg, vzg, out);
        if (needB)
            exact_voxel_store(gz, gyA + 1, gx, two_d, eta,
                              xg, yg, zg, vxg, vyg, vzg, out);
    } else {
        // common path: all nine forces are zero for both centers
        #pragma unroll
        for (int k = 0; k < 9; k++) {
            out[k * NTOT + gidxA] = 0.f;
            out[k * NTOT + gidxB] = 0.f;
        }
    }
}

extern "C" void kernel_launch(void* const* d_in, const int* in_sizes, int n_in,
                              void* d_out, int out_size)
{
    const float* xg   = (const float*)d_in[0];
    const float* yg   = (const float*)d_in[1];
    const float* zg   = (const float*)d_in[2];
    const float* vxg  = (const float*)d_in[3];
    const float* vyg  = (const float*)d_in[4];
    const float* vzg  = (const float*)d_in[5];
    const float* dptr = (const float*)d_in[6];
    float* out = (float*)d_out;

    // ETA = 2*gamma*sqrt(KN), gamma = alpha/sqrt(alpha^2+1), alpha = -ln(0.7)/pi
    const double alpha = -log(0.7) / M_PI;
    const double gam   = alpha / sqrt(alpha * alpha + 1.0);
    const float  eta   = (float)(2.0 * gam * sqrt(500000.0));

    dim3 block(BXT, BYT, BZT);
    dim3 grid(NG / BXT, NG / VYB, NG / BZT);
    dem_kernel<<<grid, block>>>(xg, yg, zg, vxg, vyg, vzg, dptr, out, eta);
}

// round 10
// speedup vs baseline: 2.1112x; 1.3146x over previous
#include <cuda_runtime.h>
#include <math.h>

#define NG 192
#define NTOT (NG * NG * NG)
#define BX 32
#define BY 4
#define BZ 4
#define TX (BX + 4)      // 36
#define TY (BY + 4)      // 8
#define TZ (BZ + 2)      // 6 : halo only on +z (forward offsets)
#define TILE (TX * TY * TZ)   // 1728

#define KN   500000.0f
#define MU   0.5f
#define EPSF 1e-4f
#define FULLMASK 0xffffffffu
#define BMASK 0x00FEFEFEu

// pair-hit flags; zero-initialized at load; pass B restores zeros every run,
// so graph replays are deterministic. No dynamic allocation.
__device__ unsigned char g_flag[NTOT];

__device__ __forceinline__ int wrapN(int v) {
    if (v < 0) v += NG;
    if (v >= NG) v -= NG;
    return v;
}

// exact per-voxel evaluation + store (pass B, only for true-hit voxels)
__device__ __noinline__ void exact_voxel_store(
    int ga, int gb, int gc, float two_d, float eta,
    const float* __restrict__ xg, const float* __restrict__ yg,
    const float* __restrict__ zg, const float* __restrict__ vxg,
    const float* __restrict__ vyg, const float* __restrict__ vzg,
    float* __restrict__ out)
{
    const float two_d2 = two_d * two_d;
    const int gidx = (ga * NG + gb) * NG + gc;
    const float px = xg[gidx], py = yg[gidx], pz = zg[gidx];
    const float pvx = vxg[gidx], pvy = vyg[gidx], pvz = vzg[gidx];
    float fxc = 0.f, fyc = 0.f, fzc = 0.f;
    float fxd = 0.f, fyd = 0.f, fzd = 0.f;
    float frx = 0.f, fry = 0.f, frz = 0.f;
    #pragma unroll 1
    for (int oz = -2; oz <= 2; oz++) {
        const int na = wrapN(ga + oz);
        #pragma unroll 1
        for (int oy = -2; oy <= 2; oy++) {
            const int nb = wrapN(gb + oy);
            const int rowb = (na * NG + nb) * NG;
            #pragma unroll 1
            for (int ox = -2; ox <= 2; ox++) {
                const int nc = wrapN(gc + ox);
                const int nidx = rowb + nc;
                const float dx = px - xg[nidx];
                const float dy = py - yg[nidx];
                const float dz = pz - zg[nidx];
                const float d2 = fmaf(dz, dz, fmaf(dy, dy, dx * dx));
                // d2 == 0 (incl. self) contributes exactly 0 -> skip
                const bool hit = (d2 < two_d2) && (d2 > 0.0f);
                if (hit) {
                    const float dist = sqrtf(d2);
                    const float safe = fmaxf(EPSF, dist);
                    const float inv  = 1.0f / safe;
                    const float coef = KN * (dist - two_d) * inv;
                    fxc += coef * dx;
                    fyc += coef * dy;
                    fzc += coef * dz;
                    const float dvx = pvx - vxg[nidx];
                    const float dvy = pvy - vyg[nidx];
                    const float dvz = pvz - vzg[nidx];
                    const float vn  = (dvx * dx + dvy * dy + dvz * dz) * inv;
                    const float c2  = eta * vn * inv;
                    fxd += c2 * dx;
                    fyd += c2 * dy;
                    fzd += c2 * dz;
                }
            }
        }
    }
    // friction: only the LAST scan shift s=(2,2,2) survives, i.e. neighbor
    // offset (-2,-2,-2), evaluated against the fully accumulated sums.
    // NOTE: includes d2 == 0 overlaps (no d2 > 0 exclusion here).
    {
        const int na = wrapN(ga - 2);
        const int nb = wrapN(gb - 2);
        const int nc = wrapN(gc - 2);
        const int nidx = (na * NG + nb) * NG + nc;
        const float dx = px - xg[nidx];
        const float dy = py - yg[nidx];
        const float dz = pz - zg[nidx];
        const float d2 = fmaf(dz, dz, fmaf(dy, dy, dx * dx));
        if (d2 < two_d2) {
            const float dvx = pvx - vxg[nidx];
            const float dvy = pvy - vyg[nidx];
            const float dvz = pvz - vzg[nidx];
            frx = -(fabsf(fabsf(MU * fyc) + fabsf(MU * fzc) - MU * fxd)
                    * dvx / fmaxf(EPSF, fabsf(dvx)));
            fry = -(fabsf(fabsf(MU * fxc) + fabsf(MU * fzc) - MU * fyd)
                    * dvy / fmaxf(EPSF, fabsf(dvy)));
            // NB: reference uses diffvy in the z-friction numerator (kept).
            frz = -(fabsf(fabsf(MU * fxc) + fabsf(MU * fyc) - MU * fzd)
                    * dvy / fmaxf(EPSF, fabsf(dvz)));
        }
    }
    float* o = out + gidx;
    o[0 * NTOT] = fxc;
    o[1 * NTOT] = fyc;
    o[2 * NTOT] = fzc;
    o[3 * NTOT] = fxd;
    o[4 * NTOT] = fyd;
    o[5 * NTOT] = fzd;
    o[6 * NTOT] = frx;
    o[7 * NTOT] = fry;
    o[8 * NTOT] = frz;
}

// ---------------- Pass A: forward-only filter + zero-store + flagging -------
__global__ __launch_bounds__(BX * BY * BZ, 4)
void filter_kernel(const float* __restrict__ xg, const float* __restrict__ yg,
                   const float* __restrict__ zg,
                   const float* __restrict__ dptr, float* __restrict__ out)
{
    __shared__ unsigned qpk[TILE];   // bytes: (floor x, floor y, floor z, 0)

    const int lx = threadIdx.x, ly = threadIdx.y, lz = threadIdx.z;
    const int bx0 = blockIdx.x * BX;
    const int by0 = blockIdx.y * BY;
    const int bz0 = blockIdx.z * BZ;
    const int tid = (lz * BY + ly) * BX + lx;

    // halo key build: x,y wrap +-2; z only 0..+2 above (forward offsets)
    for (int idx = tid; idx < TILE; idx += BX * BY * BZ) {
        int tx = idx % TX;
        int r  = idx / TX;
        int ty = r % TY;
        int tz = r / TY;
        int gx = wrapN(bx0 + tx - 2);
        int gy = wrapN(by0 + ty - 2);
        int gz = wrapN(bz0 + tz);
        int g = (gz * NG + gy) * NG + gx;
        qpk[idx] = (unsigned)(int)xg[g] | ((unsigned)(int)yg[g] << 8)
                 | ((unsigned)(int)zg[g] << 16);
    }
    __syncthreads();

    const float d     = *dptr;
    const float two_d = 2.0f * d;
    // byte-filter validity: |dx| < two_d <= 1 => |floor diff| <= 1 per axis
    const bool filter_ok = (two_d <= 1.0f);

    const int cz = lz, cy = ly + 2, cx = lx + 2;   // own z at tile tz = lz
    const int cidx = (cz * TY + cy) * TX + cx;
    const unsigned pq = qpk[cidx];

    const int gz = bz0 + lz, gy = by0 + ly, gx = bx0 + lx;
    const int gidx = (gz * NG + gy) * NG + gx;

    // ---- byte prefilter over the 62 lexicographically-forward offsets ----
    bool need = !filter_ok;
    if (filter_ok) {
        unsigned m0 = ~0u, m1 = ~0u, m2 = ~0u, m3 = ~0u;
        int k = 0;
        #pragma unroll
        for (int oz = 0; oz <= 2; oz++) {
            #pragma unroll
            for (int oy = -2; oy <= 2; oy++) {
                if (oz == 0 && oy < 0) continue;
                #pragma unroll
                for (int ox = -2; ox <= 2; ox++) {
                    if (oz == 0 && oy == 0 && ox < 1) continue;
                    const unsigned nq = qpk[cidx + (oz * TY + oy) * TX + ox];
                    const unsigned v = __vabsdiffu4(pq, nq) & BMASK;
                    const int lane = (k++) & 3;
                    if (lane == 0)      m0 = min(m0, v);
                    else if (lane == 1) m1 = min(m1, v);
                    else if (lane == 2) m2 = min(m2, v);
                    else                m3 = min(m3, v);
                }
            }
        }
        need = (min(min(m0, m1), min(m2, m3)) == 0u);
    }

    // zero all nine outputs for every voxel; pass B overwrites true hits
    float* o = out + gidx;
    #pragma unroll
    for (int q = 0; q < 9; q++) o[q * NTOT] = 0.f;

    // rare (~0.8% of warps): exact forward check; flag BOTH pair endpoints
    if (__any_sync(FULLMASK, need)) {
        if (need) {
            const float two_d2 = two_d * two_d;
            const float px = xg[gidx], py = yg[gidx], pz = zg[gidx];
            #pragma unroll 1
            for (int oz = 0; oz <= 2; oz++) {
                #pragma unroll 1
                for (int oy = -2; oy <= 2; oy++) {
                    if (oz == 0 && oy < 0) continue;
                    #pragma unroll 1
                    for (int ox = -2; ox <= 2; ox++) {
                        if (oz == 0 && oy == 0 && ox < 1) continue;
                        const int nidx = (wrapN(gz + oz) * NG + wrapN(gy + oy)) * NG
                                       + wrapN(gx + ox);
                        const float dx = px - xg[nidx];
                        const float dy = py - yg[nidx];
                        const float dz = pz - zg[nidx];
                        const float d2 = fmaf(dz, dz, fmaf(dy, dy, dx * dx));
                        // include d2 == 0: friction needs zero-distance overlaps
                        if (d2 < two_d2) {
                            g_flag[gidx] = 1;
                            g_flag[nidx] = 1;
                        }
                    }
                }
            }
        }
    }
}

// ---------------- Pass B: fix up flagged voxels, clear flags ----------------
__global__ __launch_bounds__(256)
void fixup_kernel(const float* __restrict__ xg, const float* __restrict__ yg,
                  const float* __restrict__ zg, const float* __restrict__ vxg,
                  const float* __restrict__ vyg, const float* __restrict__ vzg,
                  const float* __restrict__ dptr, float* __restrict__ out,
                  float eta)
{
    const int t = blockIdx.x * 256 + threadIdx.x;   // t < NTOT/16
    uint4 f = ((const uint4*)g_flag)[t];
    if (f.x | f.y | f.z | f.w) {
        const float two_d = 2.0f * (*dptr);
        const int base = t * 16;
        #pragma unroll 1
        for (int c = 0; c < 16; c++) {
            const unsigned w = (c < 4) ? f.x : (c < 8) ? f.y : (c < 12) ? f.z : f.w;
            if ((w >> (8 * (c & 3))) & 0xFFu) {
                const int v = base + c;
                const int gx = v % NG;
                const int r  = v / NG;
                const int gy = r % NG;
                const int gz = r / NG;
                exact_voxel_store(gz, gy, gx, two_d, eta,
                                  xg, yg, zg, vxg, vyg, vzg, out);
            }
        }
        ((uint4*)g_flag)[t] = make_uint4(0, 0, 0, 0);   // restore invariant
    }
}

extern "C" void kernel_launch(void* const* d_in, const int* in_sizes, int n_in,
                              void* d_out, int out_size)
{
    const float* xg   = (const float*)d_in[0];
    const float* yg   = (const float*)d_in[1];
    const float* zg   = (const float*)d_in[2];
    const float* vxg  = (const float*)d_in[3];
    const float* vyg  = (const float*)d_in[4];
    const float* vzg  = (const float*)d_in[5];
    const float* dptr = (const float*)d_in[6];
    float* out = (float*)d_out;

    // ETA = 2*gamma*sqrt(KN), gamma = alpha/sqrt(alpha^2+1), alpha = -ln(0.7)/pi
    const double alpha = -log(0.7) / M_PI;
    const double gam   = alpha / sqrt(alpha * alpha + 1.0);
    const float  eta   = (float)(2.0 * gam * sqrt(500000.0));

    dim3 blockA(BX, BY, BZ);
    dim3 gridA(NG / BX, NG / BY, NG / BZ);
    filter_kernel<<<gridA, blockA>>>(xg, yg, zg, dptr, out);

    const int nchunks = NTOT / 16;          // 442368
    fixup_kernel<<<nchunks / 256, 256>>>(xg, yg, zg, vxg, vyg, vzg,
                                         dptr, out, eta);
}